// round 1
// baseline (speedup 1.0000x reference)
#include <cuda_runtime.h>
#include <stdint.h>

#define N_NODES 100000
#define N_EDGES 800000
#define HIDDEN  128

// ---------------- scratch (static device memory; no allocation) -------------
__device__ float g_S1[(size_t)N_NODES * HIDDEN];   // sum over edges (i,j) of h[j], indexed by i
__device__ float g_S2[(size_t)N_NODES * HIDDEN];   // sum over edges (i,j) of h[i], indexed by j
__device__ int   g_d1[N_NODES];                    // out-degree
__device__ int   g_d2[N_NODES];                    // in-degree

// ---------------- helpers ---------------------------------------------------
__device__ __forceinline__ unsigned long long pack2(float lo, float hi) {
    unsigned long long r;
    asm("mov.b64 %0, {%1, %2};" : "=l"(r) : "f"(lo), "f"(hi));
    return r;
}
__device__ __forceinline__ float2 unpack2(unsigned long long v) {
    float2 f;
    asm("mov.b64 {%0, %1}, %2;" : "=f"(f.x), "=f"(f.y) : "l"(v));
    return f;
}
__device__ __forceinline__ void fma2(unsigned long long& acc,
                                     unsigned long long a,
                                     unsigned long long b) {
    asm("fma.rn.f32x2 %0, %1, %2, %0;" : "+l"(acc) : "l"(a), "l"(b));
}

// ---------------- kernel 1: zero scratch ------------------------------------
__global__ void zero_kernel() {
    size_t tid    = (size_t)blockIdx.x * blockDim.x + threadIdx.x;
    size_t stride = (size_t)gridDim.x * blockDim.x;
    const size_t n4 = (size_t)N_NODES * HIDDEN / 4;
    float4 z = make_float4(0.f, 0.f, 0.f, 0.f);
    for (size_t j = tid; j < n4; j += stride) {
        ((float4*)g_S1)[j] = z;
        ((float4*)g_S2)[j] = z;
    }
    for (size_t j = tid; j < N_NODES; j += stride) {
        g_d1[j] = 0;
        g_d2[j] = 0;
    }
}

// ---------------- kernel 2: edge aggregation (one warp per edge) ------------
__global__ void __launch_bounds__(256) edge_kernel(const float* __restrict__ h,
                                                   const int*   __restrict__ esrc,
                                                   const int*   __restrict__ edst) {
    int warp = (blockIdx.x * blockDim.x + threadIdx.x) >> 5;
    int lane = threadIdx.x & 31;
    if (warp >= N_EDGES) return;

    int s = esrc[warp];
    int d = edst[warp];

    // gather h[d], h[s]  (32 lanes x float4 = 128 floats each)
    float4 vd = ((const float4*)(h + (size_t)d * HIDDEN))[lane];
    float4 vs = ((const float4*)(h + (size_t)s * HIDDEN))[lane];

    // scatter-add with vector atomics (sm_90+)
    atomicAdd(((float4*)(g_S1 + (size_t)s * HIDDEN)) + lane, vd);
    atomicAdd(((float4*)(g_S2 + (size_t)d * HIDDEN)) + lane, vs);

    if (lane == 0)      atomicAdd(&g_d1[s], 1);
    else if (lane == 1) atomicAdd(&g_d2[d], 1);
}

// ---------------- kernel 3: fused GEMM + bias + relu ------------------------
// out[i] = relu( S1[i]@Ww^T + d1[i]*Wb + h[i]@Wsw^T + Wsb + S2[i]@Wtw^T + d2[i]*Wtb )
// Tile: 64 rows x 128 cols per block, 256 threads, thread tile 8 rows x 4 cols.
// Accumulators are f32x2 pairs over adjacent rows -> fma.rn.f32x2.
__global__ void __launch_bounds__(256) gemm_kernel(const float* __restrict__ h,
                                                   const float* __restrict__ Ww,
                                                   const float* __restrict__ Wb,
                                                   const float* __restrict__ Wsw,
                                                   const float* __restrict__ Wsb,
                                                   const float* __restrict__ Wtw,
                                                   const float* __restrict__ Wtb,
                                                   float* __restrict__ out) {
    __shared__ float As[32][68];    // [k][row]  (stride 68: 16B-aligned rows, bank-skewed)
    __shared__ float Ws[32][132];   // [k][col]

    const int tid = threadIdx.x;
    const int tx  = tid & 31;       // col group: cols tx*4 .. tx*4+3
    const int ty  = tid >> 5;       // row group: rows ty*8 .. ty*8+7
    const int row0 = blockIdx.x * 64;

    unsigned long long acc[4][4];   // [row-pair][col]; each = {even_row, odd_row}
#pragma unroll
    for (int p = 0; p < 4; ++p)
#pragma unroll
        for (int c = 0; c < 4; ++c) acc[p][c] = 0ull;

#pragma unroll 1
    for (int chunk = 0; chunk < 12; ++chunk) {
        const int sidx = chunk >> 2;          // 0: S1/Ww, 1: h/Wsw, 2: S2/Wtw
        const int k0   = (chunk & 3) * 32;
        const float* A = (sidx == 0) ? g_S1 : (sidx == 1) ? h : g_S2;
        const float* W = (sidx == 0) ? Ww   : (sidx == 1) ? Wsw : Wtw;

        __syncthreads();
        // load A tile: 64 rows x 32 k  (512 float4, 2 per thread)
#pragma unroll
        for (int j = 0; j < 2; ++j) {
            int lin = tid + j * 256;          // 0..511
            int r   = lin >> 3;               // 0..63
            int g   = lin & 7;                // float4 group in k
            float4 v = make_float4(0.f, 0.f, 0.f, 0.f);
            int row = row0 + r;
            if (row < N_NODES)
                v = *(const float4*)(A + (size_t)row * HIDDEN + k0 + g * 4);
            int kk = g * 4;
            As[kk + 0][r] = v.x;
            As[kk + 1][r] = v.y;
            As[kk + 2][r] = v.z;
            As[kk + 3][r] = v.w;
        }
        // load W tile: 128 cols x 32 k (1024 float4, 4 per thread); Ws[kk][c] = W[c*128 + k0+kk]
#pragma unroll
        for (int j = 0; j < 4; ++j) {
            int lin = tid + j * 256;          // 0..1023
            int c   = lin >> 3;               // 0..127
            int g   = lin & 7;
            float4 v = *(const float4*)(W + (size_t)c * HIDDEN + k0 + g * 4);
            int kk = g * 4;
            Ws[kk + 0][c] = v.x;
            Ws[kk + 1][c] = v.y;
            Ws[kk + 2][c] = v.z;
            Ws[kk + 3][c] = v.w;
        }
        __syncthreads();

#pragma unroll
        for (int kk = 0; kk < 32; ++kk) {
            // 8 A rows as 4 packed pairs (128-bit smem loads, already packed)
            ulonglong2 a01 = *(const ulonglong2*)&As[kk][ty * 8];
            ulonglong2 a23 = *(const ulonglong2*)&As[kk][ty * 8 + 4];
            float4 w = *(const float4*)&Ws[kk][tx * 4];
            unsigned long long w0 = pack2(w.x, w.x);
            unsigned long long w1 = pack2(w.y, w.y);
            unsigned long long w2 = pack2(w.z, w.z);
            unsigned long long w3 = pack2(w.w, w.w);

            fma2(acc[0][0], a01.x, w0); fma2(acc[0][1], a01.x, w1);
            fma2(acc[0][2], a01.x, w2); fma2(acc[0][3], a01.x, w3);
            fma2(acc[1][0], a01.y, w0); fma2(acc[1][1], a01.y, w1);
            fma2(acc[1][2], a01.y, w2); fma2(acc[1][3], a01.y, w3);
            fma2(acc[2][0], a23.x, w0); fma2(acc[2][1], a23.x, w1);
            fma2(acc[2][2], a23.x, w2); fma2(acc[2][3], a23.x, w3);
            fma2(acc[3][0], a23.y, w0); fma2(acc[3][1], a23.y, w1);
            fma2(acc[3][2], a23.y, w2); fma2(acc[3][3], a23.y, w3);
        }
    }

    // epilogue: bias (degree-scaled) + relu, float4 stores
    const int colbase = tx * 4;
    float4 bw  = *(const float4*)(Wb  + colbase);
    float4 bs  = *(const float4*)(Wsb + colbase);
    float4 bt  = *(const float4*)(Wtb + colbase);

#pragma unroll
    for (int p = 0; p < 4; ++p) {
        int re = row0 + ty * 8 + 2 * p;
        if (re >= N_NODES) break;
        float2 v0 = unpack2(acc[p][0]);
        float2 v1 = unpack2(acc[p][1]);
        float2 v2 = unpack2(acc[p][2]);
        float2 v3 = unpack2(acc[p][3]);

        {
            float f1 = (float)g_d1[re];
            float f2 = (float)g_d2[re];
            float4 o;
            o.x = v0.x + f1 * bw.x + bs.x + f2 * bt.x;
            o.y = v1.x + f1 * bw.y + bs.y + f2 * bt.y;
            o.z = v2.x + f1 * bw.z + bs.z + f2 * bt.z;
            o.w = v3.x + f1 * bw.w + bs.w + f2 * bt.w;
            o.x = fmaxf(o.x, 0.f); o.y = fmaxf(o.y, 0.f);
            o.z = fmaxf(o.z, 0.f); o.w = fmaxf(o.w, 0.f);
            *(float4*)(out + (size_t)re * HIDDEN + colbase) = o;
        }
        int ro = re + 1;
        if (ro < N_NODES) {
            float f1 = (float)g_d1[ro];
            float f2 = (float)g_d2[ro];
            float4 o;
            o.x = v0.y + f1 * bw.x + bs.x + f2 * bt.x;
            o.y = v1.y + f1 * bw.y + bs.y + f2 * bt.y;
            o.z = v2.y + f1 * bw.z + bs.z + f2 * bt.z;
            o.w = v3.y + f1 * bw.w + bs.w + f2 * bt.w;
            o.x = fmaxf(o.x, 0.f); o.y = fmaxf(o.y, 0.f);
            o.z = fmaxf(o.z, 0.f); o.w = fmaxf(o.w, 0.f);
            *(float4*)(out + (size_t)ro * HIDDEN + colbase) = o;
        }
    }
}

// ---------------- launch -----------------------------------------------------
extern "C" void kernel_launch(void* const* d_in, const int* in_sizes, int n_in,
                              void* d_out, int out_size) {
    const float* h    = (const float*)d_in[0];
    const int*   esrc = (const int*)  d_in[1];
    const int*   edst = (const int*)  d_in[2];
    const float* Ww   = (const float*)d_in[3];
    const float* Wb   = (const float*)d_in[4];
    const float* Wsw  = (const float*)d_in[5];
    const float* Wsb  = (const float*)d_in[6];
    const float* Wtw  = (const float*)d_in[7];
    const float* Wtb  = (const float*)d_in[8];
    float* out = (float*)d_out;

    zero_kernel<<<2048, 256>>>();
    edge_kernel<<<(N_EDGES + 7) / 8, 256>>>(h, esrc, edst);
    gemm_kernel<<<(N_NODES + 63) / 64, 256>>>(h, Ww, Wb, Wsw, Wsb, Wtw, Wtb, out);
}